// round 7
// baseline (speedup 1.0000x reference)
#include <cuda_runtime.h>

#define NH   10
#define NL   10
#define TPB  128

// ---- raw weight layout in cw (float offsets) ----
#define OFF_W0   0
#define OFF_B0   30
#define OFF_W1   40
#define OFF_B1   140
#define OFF_WR1  150
#define OFF_BR1  1150
#define OFF_WR2  1250
#define OFF_BR2  2250
#define OFF_WR3  2350
#define OFF_BR3  3350
#define OFF_W8   3450
#define OFF_B8   3550
#define OFF_W9   3560
#define OFF_B9   3570
#define CW_TOTAL 3572
// cdup float2 regions
#define B23_OFF  3572            // (BR2+BR3) dup pairs, [10][10]
#define CDUP_TOT 3672

__constant__ __align__(16) float  cw[CW_TOTAL];
__constant__ __align__(16) float2 cdup[CDUP_TOT];          // duplicated pairs (w,w)
__device__   __align__(16) float2 dupbuf[CDUP_TOT];        // staging for cdup

__device__ __forceinline__ float2 f2(float x, float y) { return make_float2(x, y); }

// packed fp32x2 FMA (Blackwell FFMA2)
__device__ __forceinline__ float2 ffma2(float2 a, float2 b, float2 c) {
    float2 d;
    asm("{\n\t"
        ".reg .b64 ra, rb, rc, rd;\n\t"
        "mov.b64 ra, {%2, %3};\n\t"
        "mov.b64 rb, {%4, %5};\n\t"
        "mov.b64 rc, {%6, %7};\n\t"
        "fma.rn.f32x2 rd, ra, rb, rc;\n\t"
        "mov.b64 {%0, %1}, rd;\n\t"
        "}"
        : "=f"(d.x), "=f"(d.y)
        : "f"(a.x), "f"(a.y), "f"(b.x), "f"(b.y), "f"(c.x), "f"(c.y));
    return d;
}
__device__ __forceinline__ float2 relu2(float2 v) {
    return f2(fmaxf(v.x, 0.0f), fmaxf(v.y, 0.0f));
}

// load 2 dup pairs (16B) from the constant dup table — warp-uniform address,
// promotable to LDCU/uniform path (separate port, no vector-RF pressure).
__device__ __forceinline__ float4 ldc4(int i) {
    return *reinterpret_cast<const float4*>(&cdup[i]);
}

// dense + relu, point-pair packed (reads ALL of h before writing out -> in-place safe)
template<int K>
__device__ __forceinline__ void dense(int Woff, int Boff,
                                      const float2 (&h)[2][K], float2 (&out)[2][NH])
{
    float2 acc[2][NH];
#pragma unroll
    for (int j2 = 0; j2 < NH/2; j2++) {            // k=0 folds bias as addend
        float4 b = ldc4(Boff + 2*j2);
        float4 w = ldc4(Woff + 2*j2);
#pragma unroll
        for (int pp = 0; pp < 2; pp++) {
            acc[pp][2*j2+0] = ffma2(h[pp][0], f2(w.x, w.y), f2(b.x, b.y));
            acc[pp][2*j2+1] = ffma2(h[pp][0], f2(w.z, w.w), f2(b.z, b.w));
        }
    }
#pragma unroll
    for (int k = 1; k < K; k++) {
#pragma unroll
        for (int j2 = 0; j2 < NH/2; j2++) {
            float4 w = ldc4(Woff + k*NH + 2*j2);
#pragma unroll
            for (int pp = 0; pp < 2; pp++) {
                acc[pp][2*j2+0] = ffma2(h[pp][k], f2(w.x, w.y), acc[pp][2*j2+0]);
                acc[pp][2*j2+1] = ffma2(h[pp][k], f2(w.z, w.w), acc[pp][2*j2+1]);
            }
        }
    }
#pragma unroll
    for (int pp = 0; pp < 2; pp++)
#pragma unroll
        for (int j = 0; j < NH; j++)
            out[pp][j] = relu2(acc[pp][j]);
}

// residual: out = relu( h1 @ W3 + h0 @ W2 + (B2+B3) ) — all constant loads
__device__ __forceinline__ void dense_res(int W3o, int W2o, int B23o,
                                          const float2 (&h1)[2][NH],
                                          const float2 (&h0)[2][NH],
                                          float2 (&out)[2][NH])
{
    float2 acc[2][NH];
#pragma unroll
    for (int j2 = 0; j2 < NH/2; j2++) {
        float4 b = ldc4(B23o + 2*j2);
        float4 w = ldc4(W3o + 2*j2);                 // k=0 of W3
#pragma unroll
        for (int pp = 0; pp < 2; pp++) {
            acc[pp][2*j2+0] = ffma2(h1[pp][0], f2(w.x, w.y), f2(b.x, b.y));
            acc[pp][2*j2+1] = ffma2(h1[pp][0], f2(w.z, w.w), f2(b.z, b.w));
        }
    }
#pragma unroll
    for (int k = 1; k < NH; k++) {
#pragma unroll
        for (int j2 = 0; j2 < NH/2; j2++) {
            float4 w = ldc4(W3o + k*NH + 2*j2);
#pragma unroll
            for (int pp = 0; pp < 2; pp++) {
                acc[pp][2*j2+0] = ffma2(h1[pp][k], f2(w.x, w.y), acc[pp][2*j2+0]);
                acc[pp][2*j2+1] = ffma2(h1[pp][k], f2(w.z, w.w), acc[pp][2*j2+1]);
            }
        }
    }
#pragma unroll
    for (int k = 0; k < NH; k++) {
#pragma unroll
        for (int j2 = 0; j2 < NH/2; j2++) {
            float4 w = ldc4(W2o + k*NH + 2*j2);
#pragma unroll
            for (int pp = 0; pp < 2; pp++) {
                acc[pp][2*j2+0] = ffma2(h0[pp][k], f2(w.x, w.y), acc[pp][2*j2+0]);
                acc[pp][2*j2+1] = ffma2(h0[pp][k], f2(w.z, w.w), acc[pp][2*j2+1]);
            }
        }
    }
#pragma unroll
    for (int pp = 0; pp < 2; pp++)
#pragma unroll
        for (int j = 0; j < NH; j++)
            out[pp][j] = relu2(acc[pp][j]);
}

__global__ void prep_kernel()
{
    for (int i = threadIdx.x; i < CW_TOTAL; i += blockDim.x) {
        float w = cw[i];
        dupbuf[i] = make_float2(w, w);
    }
    for (int i = threadIdx.x; i < 100; i += blockDim.x) {
        float s = cw[OFF_BR2 + i] + cw[OFF_BR3 + i];
        dupbuf[B23_OFF + i] = make_float2(s, s);
    }
}

__global__ void __launch_bounds__(TPB, 4)
resnet_kernel(const float4* __restrict__ x4, float4* __restrict__ out4, int nthreads)
{
    int t = blockIdx.x * TPB + threadIdx.x;
    if (t >= nthreads) return;

    // 4 points = 12 contiguous floats = 3 aligned float4 loads
    float4 a = x4[3*t + 0];
    float4 b = x4[3*t + 1];
    float4 c = x4[3*t + 2];
    // point-pair packed input: x[pp][k] = (pt_{2pp}[k], pt_{2pp+1}[k])
    float2 xin[2][3] = {
        { f2(a.x, a.w), f2(a.y, b.x), f2(a.z, b.y) },
        { f2(b.z, c.y), f2(b.w, c.z), f2(c.x, c.w) }
    };

    float2 h [2][NH];
    float2 h1[2][NH];

    dense<3 >(OFF_W0, OFF_B0, xin, h);
    dense<NH>(OFF_W1, OFF_B1, h,   h);

#pragma unroll 1
    for (int l = 0; l < NL; l++) {
        dense<NH>(OFF_WR1 + l*100, OFF_BR1 + l*10, h, h1);
        dense_res(OFF_WR3 + l*100, OFF_WR2 + l*100, B23_OFF + l*10, h1, h, h);
    }

    dense<NH>(OFF_W8, OFF_B8, h, h);

    // final [10]->[1], point-pair packed
    float2 b9 = cdup[OFF_B9];
    float2 oA = b9, oB = b9;
#pragma unroll
    for (int k = 0; k < NH; k++) {
        float2 wk = cdup[OFF_W9 + k];
        oA = ffma2(h[0][k], wk, oA);
        oB = ffma2(h[1][k], wk, oB);
    }
    out4[t] = make_float4(oA.x, oA.y, oB.x, oB.y);
}

extern "C" void kernel_launch(void* const* d_in, const int* in_sizes, int n_in,
                              void* d_out, int out_size)
{
    // stage raw weights into constant memory (D2D async copies: graph-capturable)
    static const int idx[14] = {1, 2, 3, 4, 5, 6, 7, 8, 9, 10, 11, 12, 13, 14};
    static const int off[14] = {OFF_W0, OFF_B0, OFF_W1, OFF_B1,
                                OFF_WR1, OFF_BR1, OFF_WR2, OFF_BR2, OFF_WR3, OFF_BR3,
                                OFF_W8, OFF_B8, OFF_W9, OFF_B9};
    static const int cnt[14] = {30, 10, 100, 10, 1000, 100, 1000, 100, 1000, 100, 100, 10, 10, 1};
    for (int i = 0; i < 14; i++) {
        cudaMemcpyToSymbolAsync(cw, d_in[idx[i]], (size_t)cnt[i] * sizeof(float),
                                (size_t)off[i] * sizeof(float),
                                cudaMemcpyDeviceToDevice, 0);
    }

    // build duplicated-pair table on device, then stage it into constant memory
    prep_kernel<<<1, 512>>>();
    void* dup_ptr = nullptr;
    cudaGetSymbolAddress(&dup_ptr, dupbuf);
    cudaMemcpyToSymbolAsync(cdup, dup_ptr, CDUP_TOT * sizeof(float2), 0,
                            cudaMemcpyDeviceToDevice, 0);

    int npts     = in_sizes[0] / 3;   // x is [N,3]
    int nthreads = npts / 4;          // 4 points per thread
    int nblocks  = (nthreads + TPB - 1) / TPB;
    resnet_kernel<<<nblocks, TPB>>>((const float4*)d_in[0], (float4*)d_out, nthreads);
}

// round 8
// speedup vs baseline: 1.3840x; 1.3840x over previous
#include <cuda_runtime.h>

#define NH   10
#define NL   10
#define TPB  128

// ---- raw weight layout in cw (float offsets) ----
#define OFF_W0   0
#define OFF_B0   30
#define OFF_W1   40
#define OFF_B1   140
#define OFF_WR1  150
#define OFF_BR1  1150
#define OFF_WR2  1250
#define OFF_BR2  2250
#define OFF_WR3  2350
#define OFF_BR3  3350
#define OFF_W8   3450
#define OFF_B8   3550
#define OFF_W9   3560
#define OFF_B9   3570
#define CW_TOTAL 3572
// cdup float2 regions
#define B23_OFF  3572            // (BR2+BR3) dup pairs, [10][10]
#define CDUP_TOT 3672

// SMEM dup table (float2 offsets, all even -> 16B-aligned float4 loads)
#define SM_W2   0                // [10][10][10] -> 1000
#define SM_W3   1000             // [10][10][10] -> 1000
#define SM_W8   2000             // [10][10]     -> 100
#define SM_B8   2100             // [10]
#define SM_B23  2110             // [10][10]     -> 100
#define SM_W0   2210             // [3][10]      -> 30
#define SM_B0   2240             // [10]
#define SM_W1   2250             // [10][10]     -> 100
#define SM_B1   2350             // [10]
#define SM_TOT  2360

__constant__ __align__(16) float  cw[CW_TOTAL];
__constant__ __align__(16) float2 cdup[CDUP_TOT];          // duplicated pairs (w,w)
__device__   __align__(16) float2 dupbuf[CDUP_TOT];        // staging for cdup

__device__ __forceinline__ float2 f2(float x, float y) { return make_float2(x, y); }

// packed fp32x2 FMA (Blackwell FFMA2)
__device__ __forceinline__ float2 ffma2(float2 a, float2 b, float2 c) {
    float2 d;
    asm("{\n\t"
        ".reg .b64 ra, rb, rc, rd;\n\t"
        "mov.b64 ra, {%2, %3};\n\t"
        "mov.b64 rb, {%4, %5};\n\t"
        "mov.b64 rc, {%6, %7};\n\t"
        "fma.rn.f32x2 rd, ra, rb, rc;\n\t"
        "mov.b64 {%0, %1}, rd;\n\t"
        "}"
        : "=f"(d.x), "=f"(d.y)
        : "f"(a.x), "f"(a.y), "f"(b.x), "f"(b.y), "f"(c.x), "f"(c.y));
    return d;
}
__device__ __forceinline__ float2 relu2(float2 v) {
    return f2(fmaxf(v.x, 0.0f), fmaxf(v.y, 0.0f));
}

// load 2 dup pairs (16B). C=true: constant port (LDC). C=false: shared (LDS).
template<bool C>
__device__ __forceinline__ float4 ldw(const float2* __restrict__ sm, int i) {
    if (C) return *reinterpret_cast<const float4*>(&cdup[i]);
    else   return *reinterpret_cast<const float4*>(&sm[i]);
}

// dense + relu, point-pair packed (reads ALL of h before writing out -> in-place safe)
template<int K, bool C>
__device__ __forceinline__ void dense(int Woff, int Boff, const float2* __restrict__ sm,
                                      const float2 (&h)[2][K], float2 (&out)[2][NH])
{
    float2 acc[2][NH];
#pragma unroll
    for (int j2 = 0; j2 < NH/2; j2++) {            // k=0 folds bias as addend
        float4 b = ldw<C>(sm, Boff + 2*j2);
        float4 w = ldw<C>(sm, Woff + 2*j2);
#pragma unroll
        for (int pp = 0; pp < 2; pp++) {
            acc[pp][2*j2+0] = ffma2(h[pp][0], f2(w.x, w.y), f2(b.x, b.y));
            acc[pp][2*j2+1] = ffma2(h[pp][0], f2(w.z, w.w), f2(b.z, b.w));
        }
    }
#pragma unroll
    for (int k = 1; k < K; k++) {
#pragma unroll
        for (int j2 = 0; j2 < NH/2; j2++) {
            float4 w = ldw<C>(sm, Woff + k*NH + 2*j2);
#pragma unroll
            for (int pp = 0; pp < 2; pp++) {
                acc[pp][2*j2+0] = ffma2(h[pp][k], f2(w.x, w.y), acc[pp][2*j2+0]);
                acc[pp][2*j2+1] = ffma2(h[pp][k], f2(w.z, w.w), acc[pp][2*j2+1]);
            }
        }
    }
#pragma unroll
    for (int pp = 0; pp < 2; pp++)
#pragma unroll
        for (int j = 0; j < NH; j++)
            out[pp][j] = relu2(acc[pp][j]);
}

// residual: out = relu( h1 @ W3 + h0 @ W2 + (B2+B3) ) — ALL from SMEM (LDS stream)
__device__ __forceinline__ void dense_res(int W3o, int W2o, int B23o,
                                          const float2* __restrict__ sm,
                                          const float2 (&h1)[2][NH],
                                          const float2 (&h0)[2][NH],
                                          float2 (&out)[2][NH])
{
    float2 acc[2][NH];
#pragma unroll
    for (int j2 = 0; j2 < NH/2; j2++) {
        float4 b = ldw<false>(sm, B23o + 2*j2);
        float4 w = ldw<false>(sm, W3o + 2*j2);       // k=0 of W3
#pragma unroll
        for (int pp = 0; pp < 2; pp++) {
            acc[pp][2*j2+0] = ffma2(h1[pp][0], f2(w.x, w.y), f2(b.x, b.y));
            acc[pp][2*j2+1] = ffma2(h1[pp][0], f2(w.z, w.w), f2(b.z, b.w));
        }
    }
#pragma unroll
    for (int k = 1; k < NH; k++) {
#pragma unroll
        for (int j2 = 0; j2 < NH/2; j2++) {
            float4 w = ldw<false>(sm, W3o + k*NH + 2*j2);
#pragma unroll
            for (int pp = 0; pp < 2; pp++) {
                acc[pp][2*j2+0] = ffma2(h1[pp][k], f2(w.x, w.y), acc[pp][2*j2+0]);
                acc[pp][2*j2+1] = ffma2(h1[pp][k], f2(w.z, w.w), acc[pp][2*j2+1]);
            }
        }
    }
#pragma unroll
    for (int k = 0; k < NH; k++) {
#pragma unroll
        for (int j2 = 0; j2 < NH/2; j2++) {
            float4 w = ldw<false>(sm, W2o + k*NH + 2*j2);
#pragma unroll
            for (int pp = 0; pp < 2; pp++) {
                acc[pp][2*j2+0] = ffma2(h0[pp][k], f2(w.x, w.y), acc[pp][2*j2+0]);
                acc[pp][2*j2+1] = ffma2(h0[pp][k], f2(w.z, w.w), acc[pp][2*j2+1]);
            }
        }
    }
#pragma unroll
    for (int pp = 0; pp < 2; pp++)
#pragma unroll
        for (int j = 0; j < NH; j++)
            out[pp][j] = relu2(acc[pp][j]);
}

__global__ void prep_kernel()
{
    for (int i = threadIdx.x; i < CW_TOTAL; i += blockDim.x) {
        float w = cw[i];
        dupbuf[i] = make_float2(w, w);
    }
    for (int i = threadIdx.x; i < 100; i += blockDim.x) {
        float s = cw[OFF_BR2 + i] + cw[OFF_BR3 + i];
        dupbuf[B23_OFF + i] = make_float2(s, s);
    }
}

__global__ void __launch_bounds__(TPB, 4)
resnet_kernel(const float4* __restrict__ x4, float4* __restrict__ out4, int nthreads)
{
    // SMEM dup table: W2, W3, W8+B8, B23, W0+B0, W1+B1  (the LDS stream)
    __shared__ __align__(16) float2 sw[SM_TOT];
    for (int i = threadIdx.x; i < 1000; i += TPB) {
        sw[SM_W2 + i] = cdup[OFF_WR2 + i];
        sw[SM_W3 + i] = cdup[OFF_WR3 + i];
    }
    for (int i = threadIdx.x; i < 110; i += TPB)
        sw[SM_W8 + i] = cdup[OFF_W8 + i];      // W8 then B8 (contiguous)
    for (int i = threadIdx.x; i < 100; i += TPB)
        sw[SM_B23 + i] = cdup[B23_OFF + i];
    for (int i = threadIdx.x; i < 150; i += TPB)
        sw[SM_W0 + i] = cdup[OFF_W0 + i];      // W0,B0,W1,B1 (contiguous in cw)
    __syncthreads();

    int t = blockIdx.x * TPB + threadIdx.x;
    if (t >= nthreads) return;

    // 4 points = 12 contiguous floats = 3 aligned float4 loads
    float4 a = x4[3*t + 0];
    float4 b = x4[3*t + 1];
    float4 c = x4[3*t + 2];
    // point-pair packed input: x[pp][k] = (pt_{2pp}[k], pt_{2pp+1}[k])
    float2 xin[2][3] = {
        { f2(a.x, a.w), f2(a.y, b.x), f2(a.z, b.y) },
        { f2(b.z, c.y), f2(b.w, c.z), f2(c.x, c.w) }
    };

    float2 h [2][NH];
    float2 h1[2][NH];

    dense<3,  false>(SM_W0, SM_B0, sw, xin, h);    // LDS
    dense<NH, false>(SM_W1, SM_B1, sw, h,   h);    // LDS

#pragma unroll 1
    for (int l = 0; l < NL; l++) {
        dense<NH, true>(OFF_WR1 + l*100, OFF_BR1 + l*10, sw, h, h1);   // LDC
        dense_res(SM_W3 + l*100, SM_W2 + l*100, SM_B23 + l*10,
                  sw, h1, h, h);                                        // LDS
    }

    dense<NH, false>(SM_W8, SM_B8, sw, h, h);      // LDS

    // final [10]->[1], point-pair packed (LDC, tiny)
    float2 b9 = cdup[OFF_B9];
    float2 oA = b9, oB = b9;
#pragma unroll
    for (int k = 0; k < NH; k++) {
        float2 wk = cdup[OFF_W9 + k];
        oA = ffma2(h[0][k], wk, oA);
        oB = ffma2(h[1][k], wk, oB);
    }
    out4[t] = make_float4(oA.x, oA.y, oB.x, oB.y);
}

extern "C" void kernel_launch(void* const* d_in, const int* in_sizes, int n_in,
                              void* d_out, int out_size)
{
    // stage raw weights into constant memory (D2D async copies: graph-capturable)
    static const int idx[14] = {1, 2, 3, 4, 5, 6, 7, 8, 9, 10, 11, 12, 13, 14};
    static const int off[14] = {OFF_W0, OFF_B0, OFF_W1, OFF_B1,
                                OFF_WR1, OFF_BR1, OFF_WR2, OFF_BR2, OFF_WR3, OFF_BR3,
                                OFF_W8, OFF_B8, OFF_W9, OFF_B9};
    static const int cnt[14] = {30, 10, 100, 10, 1000, 100, 1000, 100, 1000, 100, 100, 10, 10, 1};
    for (int i = 0; i < 14; i++) {
        cudaMemcpyToSymbolAsync(cw, d_in[idx[i]], (size_t)cnt[i] * sizeof(float),
                                (size_t)off[i] * sizeof(float),
                                cudaMemcpyDeviceToDevice, 0);
    }

    // build duplicated-pair table on device, then stage it into constant memory
    prep_kernel<<<1, 512>>>();
    void* dup_ptr = nullptr;
    cudaGetSymbolAddress(&dup_ptr, dupbuf);
    cudaMemcpyToSymbolAsync(cdup, dup_ptr, CDUP_TOT * sizeof(float2), 0,
                            cudaMemcpyDeviceToDevice, 0);

    int npts     = in_sizes[0] / 3;   // x is [N,3]
    int nthreads = npts / 4;          // 4 points per thread
    int nblocks  = (nthreads + TPB - 1) / TPB;
    resnet_kernel<<<nblocks, TPB>>>((const float4*)d_in[0], (float4*)d_out, nthreads);
}